// round 3
// baseline (speedup 1.0000x reference)
#include <cuda_runtime.h>
#include <cstdio>

#define DIM 1024
#define NH 16
#define HD 64
#define BATCH 2
#define LQ 2048
#define LK 2048
#define SCALE 0.125f   // HD^-0.5

// ---------------- scratch (allocation-free: __device__ globals) ----------------
__device__ float g_Qp[BATCH * LQ * DIM];
__device__ float g_Kp[BATCH * LK * DIM];
__device__ float g_Vp[BATCH * LK * DIM];
__device__ float g_Ao[BATCH * LQ * DIM];

// ---------------- fp32 GEMM: C[M,N] = A[M,K] @ W[N,K]^T + bias[N] ----------------
// BM=BN=128, BK=16, 256 threads, 8x8 micro-tile with strided rows (lane + 16*i)
// smem rows padded to 20 floats -> conflict-light float4 reads along k.
#define GBM 128
#define GBN 128
#define GBK 16
#define GPAD 20

__global__ __launch_bounds__(256) void sgemm_bias(
    const float* __restrict__ A, const float* __restrict__ W,
    const float* __restrict__ bias, float* __restrict__ C,
    int M, int N, int K)
{
    __shared__ float As[GBM * GPAD];
    __shared__ float Ws[GBN * GPAD];

    const int t  = threadIdx.x;
    const int tx = t & 15;
    const int ty = t >> 4;
    const int bn = blockIdx.x * GBN;
    const int bm = blockIdx.y * GBM;

    float acc[8][8];
#pragma unroll
    for (int i = 0; i < 8; i++)
#pragma unroll
        for (int j = 0; j < 8; j++) acc[i][j] = 0.f;

    for (int k0 = 0; k0 < K; k0 += GBK) {
        __syncthreads();
        // load A tile (128x16) and W tile (128x16): 512 float4 each, 2 per thread
#pragma unroll
        for (int r = 0; r < 2; r++) {
            int f  = t + r * 256;
            int m  = f >> 2;
            int k4 = (f & 3) * 4;
            float4 va = *(const float4*)&A[(size_t)(bm + m) * K + k0 + k4];
            *(float4*)&As[m * GPAD + k4] = va;
            float4 vw = *(const float4*)&W[(size_t)(bn + m) * K + k0 + k4];
            *(float4*)&Ws[m * GPAD + k4] = vw;
        }
        __syncthreads();

#pragma unroll
        for (int kk = 0; kk < GBK; kk += 4) {
            float4 a4[8], b4[8];
#pragma unroll
            for (int i = 0; i < 8; i++)
                a4[i] = *(const float4*)&As[(ty + 16 * i) * GPAD + kk];
#pragma unroll
            for (int j = 0; j < 8; j++)
                b4[j] = *(const float4*)&Ws[(tx + 16 * j) * GPAD + kk];
#pragma unroll
            for (int i = 0; i < 8; i++)
#pragma unroll
                for (int j = 0; j < 8; j++) {
                    acc[i][j] += a4[i].x * b4[j].x;
                    acc[i][j] += a4[i].y * b4[j].y;
                    acc[i][j] += a4[i].z * b4[j].z;
                    acc[i][j] += a4[i].w * b4[j].w;
                }
        }
    }

#pragma unroll
    for (int j = 0; j < 8; j++) {
        float bb = bias[bn + tx + 16 * j];
#pragma unroll
        for (int i = 0; i < 8; i++)
            C[(size_t)(bm + ty + 16 * i) * N + bn + tx + 16 * j] = acc[i][j] + bb;
    }
}

// ---------------- flash attention, fp32 ----------------
// One block per (q-tile of 64, head, batch). 256 threads (16x16), 4x4 micro-tiles
// with strided rows/cols. Row-major smem tiles, stride 68 (pad): float4 reads
// along head-dim/k-dim with <=2-way conflicts, no transposes anywhere.
#define APAD 68
#define ATT_SMEM_BYTES ((4 * 64 * APAD + 64) * 4)

__global__ __launch_bounds__(256) void attn_kernel(
    const float* __restrict__ Qp, const float* __restrict__ Kp,
    const float* __restrict__ Vp, const int* __restrict__ kv_mask,
    float* __restrict__ Ao)
{
    extern __shared__ float sm[];
    float* Qs = sm;                 // 64 x 68
    float* Ks = Qs + 64 * APAD;     // 64 x 68
    float* Vs = Ks + 64 * APAD;     // 64 x 68
    float* Ps = Vs + 64 * APAD;     // 64 x 68
    int*   Ms = (int*)(Ps + 64 * APAD);  // 64 ints

    const int t  = threadIdx.x;
    const int tx = t & 15;
    const int ty = t >> 4;
    const int qt = blockIdx.x;
    const int h  = blockIdx.y;
    const int b  = blockIdx.z;

    const float* Qb = Qp + ((size_t)(b * LQ + qt * 64)) * DIM + h * HD;
    const float* Kb = Kp + ((size_t)b * LK) * DIM + h * HD;
    const float* Vb = Vp + ((size_t)b * LK) * DIM + h * HD;
    const int*   mb = kv_mask + b * LK;

    // load Q tile, folding in softmax scale
#pragma unroll
    for (int r = 0; r < 4; r++) {
        int f  = t + r * 256;          // 1024 float4 = 64 rows x 16 float4
        int m  = f >> 4;
        int d4 = (f & 15) * 4;
        float4 v = *(const float4*)&Qb[(size_t)m * DIM + d4];
        v.x *= SCALE; v.y *= SCALE; v.z *= SCALE; v.w *= SCALE;
        *(float4*)&Qs[m * APAD + d4] = v;
    }

    float O[4][4];
    float mrow[4], lrow[4];
#pragma unroll
    for (int i = 0; i < 4; i++) {
        mrow[i] = -1e30f; lrow[i] = 0.f;
#pragma unroll
        for (int c = 0; c < 4; c++) O[i][c] = 0.f;
    }

    for (int kb = 0; kb < LK / 64; kb++) {
        __syncthreads();
#pragma unroll
        for (int r = 0; r < 4; r++) {
            int f  = t + r * 256;
            int m  = f >> 4;
            int d4 = (f & 15) * 4;
            *(float4*)&Ks[m * APAD + d4] =
                *(const float4*)&Kb[(size_t)(kb * 64 + m) * DIM + d4];
            *(float4*)&Vs[m * APAD + d4] =
                *(const float4*)&Vb[(size_t)(kb * 64 + m) * DIM + d4];
        }
        if (t < 64) Ms[t] = mb[kb * 64 + t];
        __syncthreads();

        // S = (Q*scale) K^T : 4x4 per thread, rows ty+16i, cols tx+16j
        float S[4][4];
#pragma unroll
        for (int i = 0; i < 4; i++)
#pragma unroll
            for (int j = 0; j < 4; j++) S[i][j] = 0.f;

#pragma unroll
        for (int d0 = 0; d0 < HD; d0 += 4) {
            float4 q4[4], k4[4];
#pragma unroll
            for (int i = 0; i < 4; i++)
                q4[i] = *(const float4*)&Qs[(ty + 16 * i) * APAD + d0];
#pragma unroll
            for (int j = 0; j < 4; j++)
                k4[j] = *(const float4*)&Ks[(tx + 16 * j) * APAD + d0];
#pragma unroll
            for (int i = 0; i < 4; i++)
#pragma unroll
                for (int j = 0; j < 4; j++) {
                    S[i][j] += q4[i].x * k4[j].x;
                    S[i][j] += q4[i].y * k4[j].y;
                    S[i][j] += q4[i].z * k4[j].z;
                    S[i][j] += q4[i].w * k4[j].w;
                }
        }

        // mask
#pragma unroll
        for (int j = 0; j < 4; j++) {
            int mv = Ms[tx + 16 * j];
            if (!mv) {
#pragma unroll
                for (int i = 0; i < 4; i++) S[i][j] = -1e30f;
            }
        }

        // online softmax (row groups of 16 lanes share a q-row)
#pragma unroll
        for (int i = 0; i < 4; i++) {
            float mx = fmaxf(fmaxf(S[i][0], S[i][1]), fmaxf(S[i][2], S[i][3]));
#pragma unroll
            for (int off = 1; off < 16; off <<= 1)
                mx = fmaxf(mx, __shfl_xor_sync(0xffffffffu, mx, off));
            float mn    = fmaxf(mrow[i], mx);
            float alpha = __expf(mrow[i] - mn);
            mrow[i] = mn;
            lrow[i] *= alpha;
#pragma unroll
            for (int c = 0; c < 4; c++) O[i][c] *= alpha;
            float s = 0.f;
#pragma unroll
            for (int j = 0; j < 4; j++) {
                float p = (S[i][j] > -1e29f) ? __expf(S[i][j] - mn) : 0.f;
                S[i][j] = p;
                s += p;
            }
#pragma unroll
            for (int off = 1; off < 16; off <<= 1)
                s += __shfl_xor_sync(0xffffffffu, s, off);
            lrow[i] += s;
        }

        // publish P
#pragma unroll
        for (int i = 0; i < 4; i++)
#pragma unroll
            for (int j = 0; j < 4; j++)
                Ps[(ty + 16 * i) * APAD + tx + 16 * j] = S[i][j];
        __syncthreads();

        // O += P @ V : O rows ty+16i, cols tx*4..tx*4+3
#pragma unroll
        for (int n0 = 0; n0 < 64; n0 += 4) {
            float4 p4[4], v4[4];
#pragma unroll
            for (int i = 0; i < 4; i++)
                p4[i] = *(const float4*)&Ps[(ty + 16 * i) * APAD + n0];
#pragma unroll
            for (int s = 0; s < 4; s++)
                v4[s] = *(const float4*)&Vs[(n0 + s) * APAD + tx * 4];
#pragma unroll
            for (int i = 0; i < 4; i++) {
                O[i][0] += p4[i].x * v4[0].x + p4[i].y * v4[1].x
                         + p4[i].z * v4[2].x + p4[i].w * v4[3].x;
                O[i][1] += p4[i].x * v4[0].y + p4[i].y * v4[1].y
                         + p4[i].z * v4[2].y + p4[i].w * v4[3].y;
                O[i][2] += p4[i].x * v4[0].z + p4[i].y * v4[1].z
                         + p4[i].z * v4[2].z + p4[i].w * v4[3].z;
                O[i][3] += p4[i].x * v4[0].w + p4[i].y * v4[1].w
                         + p4[i].z * v4[2].w + p4[i].w * v4[3].w;
            }
        }
    }

    // epilogue: O / l
    float* Ob = Ao + ((size_t)(b * LQ + qt * 64)) * DIM + h * HD;
#pragma unroll
    for (int i = 0; i < 4; i++) {
        float inv = 1.f / lrow[i];
        float4 o;
        o.x = O[i][0] * inv;
        o.y = O[i][1] * inv;
        o.z = O[i][2] * inv;
        o.w = O[i][3] * inv;
        *(float4*)&Ob[(size_t)(ty + 16 * i) * DIM + tx * 4] = o;
    }
}

// ---------------- launch ----------------
extern "C" void kernel_launch(void* const* d_in, const int* in_sizes, int n_in,
                              void* d_out, int out_size)
{
    const float* q       = (const float*)d_in[0];
    const float* k       = (const float*)d_in[1];
    const float* v       = (const float*)d_in[2];
    const int*   kv_mask = (const int*)d_in[3];
    const float* Wq      = (const float*)d_in[4];
    const float* bq      = (const float*)d_in[5];
    const float* Wk      = (const float*)d_in[6];
    const float* bk      = (const float*)d_in[7];
    const float* Wv      = (const float*)d_in[8];
    const float* bv      = (const float*)d_in[9];
    const float* Wo      = (const float*)d_in[10];
    const float* bo      = (const float*)d_in[11];
    float* out = (float*)d_out;

    float *Qp, *Kp, *Vp, *Ao;
    cudaGetSymbolAddress((void**)&Qp, g_Qp);
    cudaGetSymbolAddress((void**)&Kp, g_Kp);
    cudaGetSymbolAddress((void**)&Vp, g_Vp);
    cudaGetSymbolAddress((void**)&Ao, g_Ao);

    cudaFuncSetAttribute(attn_kernel,
                         cudaFuncAttributeMaxDynamicSharedMemorySize,
                         ATT_SMEM_BYTES);

    dim3 ggrid(DIM / GBN, (BATCH * LQ) / GBM);  // (8, 32)
    sgemm_bias<<<ggrid, 256>>>(q, Wq, bq, Qp, BATCH * LQ, DIM, DIM);
    sgemm_bias<<<ggrid, 256>>>(k, Wk, bk, Kp, BATCH * LK, DIM, DIM);
    sgemm_bias<<<ggrid, 256>>>(v, Wv, bv, Vp, BATCH * LK, DIM, DIM);

    attn_kernel<<<dim3(LQ / 64, NH, BATCH), 256, ATT_SMEM_BYTES>>>(
        Qp, Kp, Vp, kv_mask, Ao);

    sgemm_bias<<<ggrid, 256>>>(Ao, Wo, bo, out, BATCH * LQ, DIM, DIM);
}

// round 4
// speedup vs baseline: 2.9570x; 2.9570x over previous
#include <cuda_runtime.h>

#define DIM 1024
#define NH 16
#define HD 64
#define BATCH 2
#define LQ 2048
#define LK 2048
#define SCALE 0.125f   // HD^-0.5

// ---------------- scratch (allocation-free: __device__ globals) ----------------
__device__ float g_Qp[BATCH * LQ * DIM];
__device__ float g_Kp[BATCH * LK * DIM];
__device__ float g_Vp[BATCH * LK * DIM];
__device__ float g_Ao[BATCH * LQ * DIM];

// ---------------- tf32 helpers ----------------
__device__ __forceinline__ unsigned f2tf(float x) {
    unsigned r;
    asm("cvt.rna.tf32.f32 %0, %1;" : "=r"(r) : "f"(x));
    return r;
}

// D += A(16x8 row) * B(8x8 col), tf32 in, f32 accum
__device__ __forceinline__ void mma8(float* c, const unsigned* a, unsigned b0, unsigned b1) {
    asm volatile(
        "mma.sync.aligned.m16n8k8.row.col.f32.tf32.tf32.f32 "
        "{%0,%1,%2,%3}, {%4,%5,%6,%7}, {%8,%9}, {%0,%1,%2,%3};"
        : "+f"(c[0]), "+f"(c[1]), "+f"(c[2]), "+f"(c[3])
        : "r"(a[0]), "r"(a[1]), "r"(a[2]), "r"(a[3]), "r"(b0), "r"(b1));
}

__device__ __forceinline__ void cp16(unsigned s, const void* g) {
    asm volatile("cp.async.cg.shared.global [%0], [%1], 16;" :: "r"(s), "l"(g));
}
__device__ __forceinline__ void cp_commit() { asm volatile("cp.async.commit_group;"); }

// ================= GEMM: C[M,N] = A[M,K] @ W[N,K]^T + bias, tf32 tensor cores =================
#define GBM 128
#define GBN 128
#define GBK 32
#define GSR 36                               // smem row stride (floats)
#define GEMM_SMEM ((2 * GBM * GSR + 2 * GBN * GSR) * 4)

__global__ __launch_bounds__(256) void gemm_tc(
    const float* __restrict__ A, const float* __restrict__ W,
    const float* __restrict__ bias, float* __restrict__ C,
    int M, int N, int K)
{
    extern __shared__ float sm[];
    float* As = sm;                          // 2 x [128 x 36]
    float* Ws = sm + 2 * GBM * GSR;          // 2 x [128 x 36]
    const unsigned sAs = (unsigned)__cvta_generic_to_shared(As);
    const unsigned sWs = (unsigned)__cvta_generic_to_shared(Ws);

    const int t = threadIdx.x;
    const int lane = t & 31;
    const int wid = t >> 5;
    const int wm = (wid >> 2) * 64;          // warp m-offset: 0 / 64
    const int wn = (wid & 3) * 32;           // warp n-offset: 0/32/64/96
    const int g = lane >> 2, c4 = lane & 3;
    const int bm = blockIdx.y * GBM, bn = blockIdx.x * GBN;

    const int srow = t >> 3;                 // staging: 32 rows per pass
    const int scol = (t & 7) * 4;

    float acc[4][4][4];
#pragma unroll
    for (int mt = 0; mt < 4; mt++)
#pragma unroll
        for (int nt = 0; nt < 4; nt++)
#pragma unroll
            for (int i = 0; i < 4; i++) acc[mt][nt][i] = 0.f;

    auto issue = [&](int kt, int buf) {
        int k0 = kt * GBK;
#pragma unroll
        for (int r = 0; r < 4; r++) {
            int row = srow + r * 32;
            cp16(sAs + (unsigned)(buf * GBM * GSR + row * GSR + scol) * 4,
                 A + (size_t)(bm + row) * K + k0 + scol);
            cp16(sWs + (unsigned)(buf * GBN * GSR + row * GSR + scol) * 4,
                 W + (size_t)(bn + row) * K + k0 + scol);
        }
        cp_commit();
    };

    const int NT = K / GBK;
    issue(0, 0);

    for (int kt = 0; kt < NT; kt++) {
        if (kt + 1 < NT) {
            issue(kt + 1, (kt + 1) & 1);
            asm volatile("cp.async.wait_group 1;");
        } else {
            asm volatile("cp.async.wait_group 0;");
        }
        __syncthreads();

        const float* Ab = As + (kt & 1) * GBM * GSR;
        const float* Wb = Ws + (kt & 1) * GBN * GSR;

#pragma unroll
        for (int ks = 0; ks < 4; ks++) {
            unsigned af[4][4], bf[4][2];
#pragma unroll
            for (int mt = 0; mt < 4; mt++) {
                const float* p = Ab + (wm + mt * 16 + g) * GSR + ks * 8 + c4;
                af[mt][0] = f2tf(p[0]);
                af[mt][2] = f2tf(p[4]);
                af[mt][1] = f2tf(p[8 * GSR]);
                af[mt][3] = f2tf(p[8 * GSR + 4]);
            }
#pragma unroll
            for (int nt = 0; nt < 4; nt++) {
                const float* p = Wb + (wn + nt * 8 + g) * GSR + ks * 8 + c4;
                bf[nt][0] = f2tf(p[0]);
                bf[nt][1] = f2tf(p[4]);
            }
#pragma unroll
            for (int mt = 0; mt < 4; mt++)
#pragma unroll
                for (int nt = 0; nt < 4; nt++)
                    mma8(acc[mt][nt], af[mt], bf[nt][0], bf[nt][1]);
        }
        __syncthreads();
    }

    // epilogue: bias + store (float2, C-frag layout)
#pragma unroll
    for (int mt = 0; mt < 4; mt++) {
        int row = bm + wm + mt * 16 + g;
#pragma unroll
        for (int nt = 0; nt < 4; nt++) {
            int col = bn + wn + nt * 8 + 2 * c4;
            float b0 = __ldg(&bias[col]);
            float b1 = __ldg(&bias[col + 1]);
            *(float2*)&C[(size_t)row * N + col] =
                make_float2(acc[mt][nt][0] + b0, acc[mt][nt][1] + b1);
            *(float2*)&C[(size_t)(row + 8) * N + col] =
                make_float2(acc[mt][nt][2] + b0, acc[mt][nt][3] + b1);
        }
    }
}

// ================= flash attention, tf32 tensor cores =================
// Block: 256 thr = 8 warps; q-tile 128 (16 rows/warp); kv tiles of 64.
#define AP 68
#define ATT_TILE (64 * AP)   // 4352 floats per K or V buffer
#define ATT_SMEM ((4 * ATT_TILE + 128 * AP) * 4 + 2 * 64 * 4)

__global__ __launch_bounds__(256) void attn_tc(
    const float* __restrict__ Qp, const float* __restrict__ Kp,
    const float* __restrict__ Vp, const int* __restrict__ kv_mask,
    float* __restrict__ Ao)
{
    extern __shared__ float sm[];
    float* Ks  = sm;                          // 2 x [64 x 68]
    float* Vs  = sm + 2 * ATT_TILE;           // 2 x [64 x 68]
    float* Ps  = sm + 4 * ATT_TILE;           // [128 x 68] (Q staging, then P)
    int*   Msm = (int*)(sm + 4 * ATT_TILE + 128 * AP);  // 2 x 64

    const unsigned sK = (unsigned)__cvta_generic_to_shared(Ks);
    const unsigned sV = (unsigned)__cvta_generic_to_shared(Vs);
    const unsigned sM = (unsigned)__cvta_generic_to_shared(Msm);

    const int t = threadIdx.x, lane = t & 31, w = t >> 5;
    const int g = lane >> 2, c4 = lane & 3;
    const int qt = blockIdx.x, h = blockIdx.y, b = blockIdx.z;

    const float* Qb = Qp + ((size_t)(b * LQ + qt * 128)) * DIM + h * HD;
    const float* Kb = Kp + (size_t)b * LK * DIM + h * HD;
    const float* Vb = Vp + (size_t)b * LK * DIM + h * HD;
    const int*   mb = kv_mask + b * LK;

    auto issue_kv = [&](int kt, int buf) {
        const float* Kg = Kb + (size_t)(kt * 64) * DIM;
        const float* Vg = Vb + (size_t)(kt * 64) * DIM;
        int d4 = (t & 15) * 4;
#pragma unroll
        for (int r = 0; r < 4; r++) {
            int row = (t >> 4) + r * 16;
            cp16(sK + (unsigned)(buf * ATT_TILE + row * AP + d4) * 4,
                 Kg + (size_t)row * DIM + d4);
            cp16(sV + (unsigned)(buf * ATT_TILE + row * AP + d4) * 4,
                 Vg + (size_t)row * DIM + d4);
        }
        if (t < 16) cp16(sM + buf * 256 + t * 16, mb + kt * 64 + t * 4);
        cp_commit();
    };

    issue_kv(0, 0);

    // stage Q (scaled) into Ps, then lift A-fragments into registers
    {
        int d4 = (t & 15) * 4;
#pragma unroll
        for (int r = 0; r < 8; r++) {
            int row = (t >> 4) + r * 16;
            float4 v = *(const float4*)(Qb + (size_t)row * DIM + d4);
            v.x *= SCALE; v.y *= SCALE; v.z *= SCALE; v.w *= SCALE;
            *(float4*)&Ps[row * AP + d4] = v;
        }
    }
    __syncthreads();

    unsigned qf[8][4];
    {
        const float* q0 = Ps + (16 * w + g) * AP + c4;
#pragma unroll
        for (int dk = 0; dk < 8; dk++) {
            qf[dk][0] = f2tf(q0[dk * 8]);
            qf[dk][2] = f2tf(q0[dk * 8 + 4]);
            qf[dk][1] = f2tf(q0[8 * AP + dk * 8]);
            qf[dk][3] = f2tf(q0[8 * AP + dk * 8 + 4]);
        }
    }

    float O[8][4];
#pragma unroll
    for (int nt = 0; nt < 8; nt++)
#pragma unroll
        for (int i = 0; i < 4; i++) O[nt][i] = 0.f;
    float mr0 = -1e30f, mr1 = -1e30f, lr0 = 0.f, lr1 = 0.f;

    for (int kt = 0; kt < LK / 64; kt++) {
        if (kt + 1 < LK / 64) {
            issue_kv(kt + 1, (kt + 1) & 1);
            asm volatile("cp.async.wait_group 1;");
        } else {
            asm volatile("cp.async.wait_group 0;");
        }
        __syncthreads();

        const float* K0 = Ks + (kt & 1) * ATT_TILE;
        const float* V0 = Vs + (kt & 1) * ATT_TILE;
        const int*   Mc = Msm + (kt & 1) * 64;

        // S = Q K^T  (16 q x 64 k per warp)
        float S[8][4];
#pragma unroll
        for (int nt = 0; nt < 8; nt++)
#pragma unroll
            for (int i = 0; i < 4; i++) S[nt][i] = 0.f;

#pragma unroll
        for (int dk = 0; dk < 8; dk++) {
#pragma unroll
            for (int nt = 0; nt < 8; nt++) {
                const float* p = K0 + (nt * 8 + g) * AP + dk * 8 + c4;
                mma8(S[nt], qf[dk], f2tf(p[0]), f2tf(p[4]));
            }
        }

        // mask
#pragma unroll
        for (int nt = 0; nt < 8; nt++) {
            if (!Mc[nt * 8 + 2 * c4])     { S[nt][0] = -1e30f; S[nt][2] = -1e30f; }
            if (!Mc[nt * 8 + 2 * c4 + 1]) { S[nt][1] = -1e30f; S[nt][3] = -1e30f; }
        }

        // online softmax on fragments: lane owns rows g and g+8 (shared by 4 lanes)
        float mx0 = -1e30f, mx1 = -1e30f;
#pragma unroll
        for (int nt = 0; nt < 8; nt++) {
            mx0 = fmaxf(mx0, fmaxf(S[nt][0], S[nt][1]));
            mx1 = fmaxf(mx1, fmaxf(S[nt][2], S[nt][3]));
        }
        mx0 = fmaxf(mx0, __shfl_xor_sync(0xffffffffu, mx0, 1));
        mx0 = fmaxf(mx0, __shfl_xor_sync(0xffffffffu, mx0, 2));
        mx1 = fmaxf(mx1, __shfl_xor_sync(0xffffffffu, mx1, 1));
        mx1 = fmaxf(mx1, __shfl_xor_sync(0xffffffffu, mx1, 2));

        float mn0 = fmaxf(mr0, mx0), mn1 = fmaxf(mr1, mx1);
        float a0 = __expf(mr0 - mn0), a1 = __expf(mr1 - mn1);
        mr0 = mn0; mr1 = mn1; lr0 *= a0; lr1 *= a1;

        float s0 = 0.f, s1 = 0.f;
#pragma unroll
        for (int nt = 0; nt < 8; nt++) {
            O[nt][0] *= a0; O[nt][1] *= a0; O[nt][2] *= a1; O[nt][3] *= a1;
            float p0 = S[nt][0] > -1e29f ? __expf(S[nt][0] - mn0) : 0.f;
            float p1 = S[nt][1] > -1e29f ? __expf(S[nt][1] - mn0) : 0.f;
            float p2 = S[nt][2] > -1e29f ? __expf(S[nt][2] - mn1) : 0.f;
            float p3 = S[nt][3] > -1e29f ? __expf(S[nt][3] - mn1) : 0.f;
            S[nt][0] = p0; S[nt][1] = p1; S[nt][2] = p2; S[nt][3] = p3;
            s0 += p0 + p1; s1 += p2 + p3;
        }
        s0 += __shfl_xor_sync(0xffffffffu, s0, 1);
        s0 += __shfl_xor_sync(0xffffffffu, s0, 2);
        s1 += __shfl_xor_sync(0xffffffffu, s1, 1);
        s1 += __shfl_xor_sync(0xffffffffu, s1, 2);
        lr0 += s0; lr1 += s1;

        // publish P to this warp's private smem slice (C-layout -> A-layout hop)
        float* Pw = Ps + (16 * w) * AP;
#pragma unroll
        for (int nt = 0; nt < 8; nt++) {
            *(float2*)&Pw[g * AP + nt * 8 + 2 * c4]       = make_float2(S[nt][0], S[nt][1]);
            *(float2*)&Pw[(g + 8) * AP + nt * 8 + 2 * c4] = make_float2(S[nt][2], S[nt][3]);
        }
        __syncwarp();

        // O += P @ V   (V consumed in natural [k][d] layout)
#pragma unroll
        for (int kk = 0; kk < 8; kk++) {
            unsigned pa[4];
            const float* pp = Pw + g * AP + kk * 8 + c4;
            pa[0] = f2tf(pp[0]);
            pa[2] = f2tf(pp[4]);
            pa[1] = f2tf(pp[8 * AP]);
            pa[3] = f2tf(pp[8 * AP + 4]);
            const float* vr0 = V0 + (kk * 8 + c4) * AP;
            const float* vr1 = V0 + (kk * 8 + 4 + c4) * AP;
#pragma unroll
            for (int nt = 0; nt < 8; nt++)
                mma8(O[nt], pa, f2tf(vr0[nt * 8 + g]), f2tf(vr1[nt * 8 + g]));
        }
        __syncthreads();
    }

    // epilogue
    float inv0 = 1.f / lr0, inv1 = 1.f / lr1;
    float* Ob = Ao + ((size_t)(b * LQ + qt * 128)) * DIM + h * HD;
    int row0 = 16 * w + g;
#pragma unroll
    for (int nt = 0; nt < 8; nt++) {
        int col = nt * 8 + 2 * c4;
        *(float2*)&Ob[(size_t)row0 * DIM + col] =
            make_float2(O[nt][0] * inv0, O[nt][1] * inv0);
        *(float2*)&Ob[(size_t)(row0 + 8) * DIM + col] =
            make_float2(O[nt][2] * inv1, O[nt][3] * inv1);
    }
}

// ---------------- launch ----------------
extern "C" void kernel_launch(void* const* d_in, const int* in_sizes, int n_in,
                              void* d_out, int out_size)
{
    const float* q       = (const float*)d_in[0];
    const float* k       = (const float*)d_in[1];
    const float* v       = (const float*)d_in[2];
    const int*   kv_mask = (const int*)d_in[3];
    const float* Wq      = (const float*)d_in[4];
    const float* bq      = (const float*)d_in[5];
    const float* Wk      = (const float*)d_in[6];
    const float* bk      = (const float*)d_in[7];
    const float* Wv      = (const float*)d_in[8];
    const float* bv      = (const float*)d_in[9];
    const float* Wo      = (const float*)d_in[10];
    const float* bo      = (const float*)d_in[11];
    float* out = (float*)d_out;

    float *Qp, *Kp, *Vp, *Ao;
    cudaGetSymbolAddress((void**)&Qp, g_Qp);
    cudaGetSymbolAddress((void**)&Kp, g_Kp);
    cudaGetSymbolAddress((void**)&Vp, g_Vp);
    cudaGetSymbolAddress((void**)&Ao, g_Ao);

    cudaFuncSetAttribute(gemm_tc, cudaFuncAttributeMaxDynamicSharedMemorySize, GEMM_SMEM);
    cudaFuncSetAttribute(attn_tc, cudaFuncAttributeMaxDynamicSharedMemorySize, ATT_SMEM);

    dim3 ggrid(DIM / GBN, (BATCH * LQ) / GBM);  // (8, 32)
    gemm_tc<<<ggrid, 256, GEMM_SMEM>>>(q, Wq, bq, Qp, BATCH * LQ, DIM, DIM);
    gemm_tc<<<ggrid, 256, GEMM_SMEM>>>(k, Wk, bk, Kp, BATCH * LK, DIM, DIM);
    gemm_tc<<<ggrid, 256, GEMM_SMEM>>>(v, Wv, bv, Vp, BATCH * LK, DIM, DIM);

    attn_tc<<<dim3(LQ / 128, NH, BATCH), 256, ATT_SMEM>>>(Qp, Kp, Vp, kv_mask, Ao);

    gemm_tc<<<ggrid, 256, GEMM_SMEM>>>(Ao, Wo, bo, out, BATCH * LQ, DIM, DIM);
}